// round 15
// baseline (speedup 1.0000x reference)
#include <cuda_runtime.h>
#include <cuda_fp16.h>
#include <cstdint>

#define NPG  1024
#define HD   64
#define FULL 0xffffffffu

__device__ __forceinline__ int prev_node(int j) {
    return ((j & (NPG - 1)) == 0) ? j + NPG - 1 : j - 1;
}

__device__ __forceinline__ uint32_t packh2(float lo, float hi) {
    __half2 h = __floats2half2_rn(lo, hi);
    return *reinterpret_cast<uint32_t*>(&h);
}

__device__ __forceinline__ float lo_of(float v) {
    return v - __half2float(__float2half_rn(v));
}

__device__ __forceinline__ uint32_t h2relu(uint32_t a) {
    __half2 r = __hmax2(*reinterpret_cast<__half2*>(&a), __float2half2_rn(0.0f));
    return *reinterpret_cast<uint32_t*>(&r);
}

__device__ __forceinline__ uint32_t h2avg(uint32_t a, uint32_t b) {
    __half2 r = __hmul2(__hadd2(*reinterpret_cast<__half2*>(&a),
                                *reinterpret_cast<__half2*>(&b)),
                        __float2half2_rn(0.5f));
    return *reinterpret_cast<uint32_t*>(&r);
}

__device__ __forceinline__ void mma_f16(float* d, uint32_t a0, uint32_t a1,
                                        uint32_t a2, uint32_t a3,
                                        uint32_t b0, uint32_t b1) {
    asm volatile(
        "mma.sync.aligned.m16n8k16.row.col.f32.f16.f16.f32 "
        "{%0,%1,%2,%3}, {%4,%5,%6,%7}, {%8,%9}, {%0,%1,%2,%3};"
        : "+f"(d[0]), "+f"(d[1]), "+f"(d[2]), "+f"(d[3])
        : "r"(a0), "r"(a1), "r"(a2), "r"(a3), "r"(b0), "r"(b1));
}

__device__ __forceinline__ uint32_t smem_u32(const void* p) {
    uint32_t a;
    asm("{ .reg .u64 t; cvta.to.shared.u64 t, %1; cvt.u32.u64 %0, t; }" : "=r"(a) : "l"(p));
    return a;
}

__device__ __forceinline__ void lds_u2(uint32_t addr, uint32_t& v0, uint32_t& v1) {
    asm volatile("ld.shared.v2.u32 {%0,%1}, [%2];" : "=r"(v0), "=r"(v1) : "r"(addr));
}

__device__ __forceinline__ void cp4(uint32_t dst, const float* src) {
    asm volatile("cp.async.ca.shared.global [%0], [%1], 4;"
                 :: "r"(dst), "l"(src) : "memory");
}

__global__ void __launch_bounds__(128, 3) gnn_warp(
    const float* __restrict__ x,
    const float* __restrict__ W1, const float* __restrict__ b1,
    const float* __restrict__ W2, const float* __restrict__ b2,
    const float* __restrict__ Wl, const float* __restrict__ bl,
    float* __restrict__ out, int nseg)
{
    __shared__ float4 w1pk[HD];     // {W1[0][c],W1[1][c],W1[2][c],b1[c]}
    __shared__ float  sb2[HD];
    __shared__ uint2  w1s[8 * 32];  // stage-1 B frags per (nb, lane)
    __shared__ uint2  hs[4 * 32];   // head B frags per (s, lane)
    __shared__ float4 ustage[2 * 4 * 32 * 2];  // x prefetch: [slot][warp][lane][2]

    const int t  = threadIdx.x;
    const int l  = t & 31;
    const int w  = t >> 5;
    const int lq = l >> 2;            // 0..7
    const int lr = l & 3;             // 0..3

    if (t < HD) {
        float4 v; v.x = W1[t]; v.y = W1[HD + t]; v.z = W1[2 * HD + t]; v.w = b1[t];
        w1pk[t] = v;
    } else if (t < 2 * HD) {
        sb2[t - HD] = b2[t - HD];
    }

    if (w == 0) {
        // ---- stage-1 B fragments (W1 hi/lo split) -> shared
        #pragma unroll
        for (int nb = 0; nb < 8; nb++) {
            int n = nb * 8 + lq;
            float w0 = W1[n], w1v = W1[HD + n], w2v = W1[2 * HD + n], bb = b1[n];
            uint32_t bhi, blo;
            if (lr == 0)      { bhi = packh2(w0, w1v);  blo = packh2(lo_of(w0), lo_of(w1v)); }
            else if (lr == 1) { bhi = packh2(w2v, bb);  blo = packh2(lo_of(w2v), lo_of(bb)); }
            else if (lr == 2) { bhi = packh2(w0, w1v);  blo = 0; }
            else              { bhi = packh2(w2v, 0.f); blo = 0; }
            w1s[nb * 32 + l] = make_uint2(bhi, blo);
        }
        // ---- head B fragments (Wl, cols 3..7 zero) -> shared
        #pragma unroll
        for (int s = 0; s < 4; s++) {
            int k0 = 16 * s + 2 * lr;
            float w00 = (lq < 3) ? Wl[k0 * 3 + lq] : 0.0f;
            float w01 = (lq < 3) ? Wl[(k0 + 1) * 3 + lq] : 0.0f;
            float w10 = (lq < 3) ? Wl[(k0 + 8) * 3 + lq] : 0.0f;
            float w11 = (lq < 3) ? Wl[(k0 + 9) * 3 + lq] : 0.0f;
            hs[s * 32 + l] = make_uint2(packh2(w00, w01), packh2(w10, w11));
        }
    }
    __syncthreads();

    const uint32_t w1s_b = smem_u32(w1s) + (uint32_t)l * 8u;
    const uint32_t hs_b  = smem_u32(hs)  + (uint32_t)l * 8u;
    // per-(warp,lane) staging base: 2 slots x 32B
    const uint32_t ust_b = smem_u32(ustage) + (uint32_t)(w * 32 + l) * 32u;
    const uint32_t ust_stride = 4u * 32u * 32u;   // slot stride in bytes

    // ---- stage-2 B fragments (W2, fp16) — register resident
    uint32_t breg[4][8][2];
    #pragma unroll
    for (int s = 0; s < 4; s++)
        #pragma unroll
        for (int nb = 0; nb < 8; nb++) {
            int n  = nb * 8 + lq;
            int k0 = 16 * s + 2 * lr;
            breg[s][nb][0] = packh2(W2[k0 * HD + n],       W2[(k0 + 1) * HD + n]);
            breg[s][nb][1] = packh2(W2[(k0 + 8) * HD + n], W2[(k0 + 9) * HD + n]);
        }

    const float bl0 = bl[0], bl1 = bl[1], bl2 = bl[2];

    // ---- contiguous run assignment (balanced remainder split)
    const int gw    = blockIdx.x * 4 + w;
    const int nwarp = gridDim.x * 4;
    const int K     = nseg / nwarp;
    const int rem   = nseg - K * nwarp;
    const int s0    = gw * K + (gw < rem ? gw : rem);
    const int s1    = s0 + K + (gw < rem ? 1 : 0);

    // ---- prefetch segment s0 into slot 0
    {
        int n = s0 * 32 + l;
        int p = prev_node(n);
        const float* xs = x + 3 * n;
        const float* xp = x + 3 * p;
        cp4(ust_b + 0,  xs + 0); cp4(ust_b + 4,  xs + 1); cp4(ust_b + 8,  xs + 2);
        cp4(ust_b + 16, xp + 0); cp4(ust_b + 20, xp + 1); cp4(ust_b + 24, xp + 2);
        asm volatile("cp.async.commit_group;" ::: "memory");
    }

    uint32_t zprev[8];   // carry: z of row (base-1); also row 15 between mb0->mb1
    int slot = 0;

    for (int seg = s0; seg < s1; seg++) {
        const int base = seg * 32;

        // ---- prefetch NEXT segment into the other slot (clamped at run end)
        {
            int nseg_next = (seg + 1 < s1) ? seg + 1 : seg;
            int n = nseg_next * 32 + l;
            int p = prev_node(n);
            const float* xs = x + 3 * n;
            const float* xp = x + 3 * p;
            uint32_t d = ust_b + (uint32_t)(slot ^ 1) * ust_stride;
            cp4(d + 0,  xs + 0); cp4(d + 4,  xs + 1); cp4(d + 8,  xs + 2);
            cp4(d + 16, xp + 0); cp4(d + 20, xp + 1); cp4(d + 24, xp + 2);
            asm volatile("cp.async.commit_group;" ::: "memory");
        }
        // current slot's group is the oldest of the 2 in flight
        asm volatile("cp.async.wait_group 1;" ::: "memory");

        // ---- read staged x, build ring-averaged u (fp32), split hi/lo
        float4 xa = ustage[(slot * 4 + w) * 64 + l * 2];       // x[n]
        float4 xb = ustage[(slot * 4 + w) * 64 + l * 2 + 1];   // x[prev(n)]
        const float ux = 0.5f * (xa.x + xb.x);
        const float uy = 0.5f * (xa.y + xb.y);
        const float uz = 0.5f * (xa.z + xb.z);
        const uint32_t uhi_xy = packh2(ux, uy);
        const uint32_t uhi_z1 = packh2(uz, 1.0f);
        const uint32_t ulo_xy = packh2(lo_of(ux), lo_of(uy));
        const uint32_t ulo_z0 = packh2(lo_of(uz), 0.0f);
        slot ^= 1;

        // ---- halo init only at run start or graph boundary (1 in 32 segs)
        if (seg == s0 || (base & (NPG - 1)) == 0) {
            const int H  = prev_node(base);
            const int pH = prev_node(H);
            const float hx = 0.5f * (x[3*H+0] + x[3*pH+0]);
            const float hy = 0.5f * (x[3*H+1] + x[3*pH+1]);
            const float hz = 0.5f * (x[3*H+2] + x[3*pH+2]);
            #pragma unroll
            for (int nb = 0; nb < 8; nb++) {
                int c0 = nb * 8 + 2 * lr;
                float4 wc0 = w1pk[c0];
                float4 wc1 = w1pk[c0 + 1];
                float h0 = fmaf(hx, wc0.x, fmaf(hy, wc0.y, fmaf(hz, wc0.z, wc0.w)));
                float h1 = fmaf(hx, wc1.x, fmaf(hy, wc1.y, fmaf(hz, wc1.z, wc1.w)));
                zprev[nb] = packh2(fmaxf(h0, 0.f), fmaxf(h1, 0.f));
            }
        }

        #pragma unroll
        for (int mb = 0; mb < 2; mb++) {
            const int r0 = 16 * mb + lq;
            const int r1 = r0 + 8;

            // ---- stage-1 A fragments: shuffle u from row lanes, select by lr
            uint32_t s0a = __shfl_sync(FULL, uhi_xy, r0);
            uint32_t s0b = __shfl_sync(FULL, uhi_z1, r0);
            uint32_t s0c = __shfl_sync(FULL, ulo_xy, r0);
            uint32_t s0d = __shfl_sync(FULL, ulo_z0, r0);
            uint32_t s1a = __shfl_sync(FULL, uhi_xy, r1);
            uint32_t s1b = __shfl_sync(FULL, uhi_z1, r1);
            uint32_t s1c = __shfl_sync(FULL, ulo_xy, r1);
            uint32_t s1d = __shfl_sync(FULL, ulo_z0, r1);
            uint32_t a0 = (lr == 0) ? s0a : (lr == 1) ? s0b : (lr == 2) ? s0c : s0d;
            uint32_t a1 = (lr == 0) ? s1a : (lr == 1) ? s1b : (lr == 2) ? s1c : s1d;
            uint32_t a2 = (lr == 0) ? s0a : (lr == 1) ? s0b : 0u;
            uint32_t a3 = (lr == 0) ? s1a : (lr == 1) ? s1b : 0u;

            // ---- stage-1 (per nb, transient accumulator, B from shared) -> al/ah
            uint32_t al[8], ah[8];
            #pragma unroll
            for (int nb = 0; nb < 8; nb++) {
                uint32_t wb0, wb1;
                lds_u2(w1s_b + (uint32_t)nb * 256u, wb0, wb1);
                float hD[4] = {0.f, 0.f, 0.f, 0.f};
                mma_f16(hD, a0, a1, a2, a3, wb0, wb1);
                uint32_t zl = h2relu(packh2(hD[0], hD[1]));  // row r0
                uint32_t zh = h2relu(packh2(hD[2], hD[3]));  // row r1
                uint32_t zls = __shfl_sync(FULL, zl, (l + 28) & 31);
                uint32_t zhs = __shfl_sync(FULL, zh, (l + 28) & 31);
                uint32_t zlp, zhp;
                if (lq == 0) {
                    zlp = zprev[nb];   // row -1 (carry/halo) or row 15
                    zhp = zls;         // row 16mb+7
                } else {
                    zlp = zls;
                    zhp = zhs;
                }
                zprev[nb] = zhs;       // lq==0 lanes: row 16mb+15 (-> mb1 / next seg)
                al[nb] = h2avg(zl, zlp);
                ah[nb] = h2avg(zh, zhp);
            }

            // ---- stage-2 + head, half-split: 4 independent MMA chains
            float d2[4] = {0.f, 0.f, 0.f, 0.f};
            #pragma unroll
            for (int h2 = 0; h2 < 2; h2++) {
                float dc[4][4];
                #pragma unroll
                for (int j = 0; j < 4; j++) {
                    dc[j][0] = 0.f; dc[j][1] = 0.f; dc[j][2] = 0.f; dc[j][3] = 0.f;
                }
                #pragma unroll
                for (int sp = 0; sp < 4; sp++) {
                    #pragma unroll
                    for (int j = 0; j < 4; j++) {
                        const int nb = 4 * h2 + j;
                        mma_f16(dc[j], al[2*sp], ah[2*sp], al[2*sp+1], ah[2*sp+1],
                                breg[sp][nb][0], breg[sp][nb][1]);
                    }
                }
                #pragma unroll
                for (int ss = 0; ss < 2; ss++) {
                    const int s  = 2 * h2 + ss;
                    const int j0 = 2 * ss, j1 = 2 * ss + 1;
                    const int n0 = 4 * h2 + j0, n1 = 4 * h2 + j1;
                    float2 bp0 = *reinterpret_cast<const float2*>(sb2 + n0 * 8 + 2 * lr);
                    float2 bp1 = *reinterpret_cast<const float2*>(sb2 + n1 * 8 + 2 * lr);
                    uint32_t e0 = packh2(fmaxf(dc[j0][0] + bp0.x, 0.f),
                                         fmaxf(dc[j0][1] + bp0.y, 0.f));
                    uint32_t e1 = packh2(fmaxf(dc[j0][2] + bp0.x, 0.f),
                                         fmaxf(dc[j0][3] + bp0.y, 0.f));
                    uint32_t e2 = packh2(fmaxf(dc[j1][0] + bp1.x, 0.f),
                                         fmaxf(dc[j1][1] + bp1.y, 0.f));
                    uint32_t e3 = packh2(fmaxf(dc[j1][2] + bp1.x, 0.f),
                                         fmaxf(dc[j1][3] + bp1.y, 0.f));
                    uint32_t hb0, hb1;
                    lds_u2(hs_b + (uint32_t)s * 256u, hb0, hb1);
                    mma_f16(d2, e0, e1, e2, e3, hb0, hb1);
                }
            }

            const int g0 = base + r0;
            const int g1 = base + r1;
            if (lr == 0) {
                out[3*g0+0] = d2[0] + bl0;
                out[3*g0+1] = d2[1] + bl1;
                out[3*g1+0] = d2[2] + bl0;
                out[3*g1+1] = d2[3] + bl1;
            } else if (lr == 1) {
                out[3*g0+2] = d2[0] + bl2;
                out[3*g1+2] = d2[2] + bl2;
            }
        }
    }
}

extern "C" void kernel_launch(void* const* d_in, const int* in_sizes, int n_in,
                              void* d_out, int out_size) {
    // metadata order: node_index, edge_index, W1, b1, W2, b2, Wl, bl
    const float* x  = (const float*)d_in[0];
    const float* W1 = (const float*)d_in[2];
    const float* b1 = (const float*)d_in[3];
    const float* W2 = (const float*)d_in[4];
    const float* b2 = (const float*)d_in[5];
    const float* Wl = (const float*)d_in[6];
    const float* bl = (const float*)d_in[7];
    float* out = (float*)d_out;

    int N    = in_sizes[0] / 3;
    int nseg = N / 32;
    int grid = 3 * 148;
    if (grid * 4 > nseg) grid = (nseg + 3) / 4;

    gnn_warp<<<grid, 128>>>(x, W1, b1, W2, b2, Wl, bl, out, nseg);
}

// round 16
// speedup vs baseline: 1.0808x; 1.0808x over previous
#include <cuda_runtime.h>
#include <cuda_fp16.h>
#include <cstdint>

#define NPG  1024
#define HD   64
#define FULL 0xffffffffu

__device__ __forceinline__ int prev_node(int j) {
    return ((j & (NPG - 1)) == 0) ? j + NPG - 1 : j - 1;
}

__device__ __forceinline__ uint32_t packh2(float lo, float hi) {
    __half2 h = __floats2half2_rn(lo, hi);
    return *reinterpret_cast<uint32_t*>(&h);
}

__device__ __forceinline__ float lo_of(float v) {
    return v - __half2float(__float2half_rn(v));
}

__device__ __forceinline__ uint32_t h2relu(uint32_t a) {
    __half2 r = __hmax2(*reinterpret_cast<__half2*>(&a), __float2half2_rn(0.0f));
    return *reinterpret_cast<uint32_t*>(&r);
}

// relu(a + b) in half2
__device__ __forceinline__ uint32_t h2addrelu(uint32_t a, uint32_t b) {
    __half2 r = __hmax2(__hadd2(*reinterpret_cast<__half2*>(&a),
                                *reinterpret_cast<__half2*>(&b)),
                        __float2half2_rn(0.0f));
    return *reinterpret_cast<uint32_t*>(&r);
}

__device__ __forceinline__ uint32_t h2avg(uint32_t a, uint32_t b) {
    __half2 r = __hmul2(__hadd2(*reinterpret_cast<__half2*>(&a),
                                *reinterpret_cast<__half2*>(&b)),
                        __float2half2_rn(0.5f));
    return *reinterpret_cast<uint32_t*>(&r);
}

__device__ __forceinline__ void mma_f16(float* d, uint32_t a0, uint32_t a1,
                                        uint32_t a2, uint32_t a3,
                                        uint32_t b0, uint32_t b1) {
    asm volatile(
        "mma.sync.aligned.m16n8k16.row.col.f32.f16.f16.f32 "
        "{%0,%1,%2,%3}, {%4,%5,%6,%7}, {%8,%9}, {%0,%1,%2,%3};"
        : "+f"(d[0]), "+f"(d[1]), "+f"(d[2]), "+f"(d[3])
        : "r"(a0), "r"(a1), "r"(a2), "r"(a3), "r"(b0), "r"(b1));
}

__device__ __forceinline__ uint32_t smem_u32(const void* p) {
    uint32_t a;
    asm("{ .reg .u64 t; cvta.to.shared.u64 t, %1; cvt.u32.u64 %0, t; }" : "=r"(a) : "l"(p));
    return a;
}

__device__ __forceinline__ void lds_u2(uint32_t addr, uint32_t& v0, uint32_t& v1) {
    asm volatile("ld.shared.v2.u32 {%0,%1}, [%2];" : "=r"(v0), "=r"(v1) : "r"(addr));
}

__device__ __forceinline__ uint32_t lds_u1(uint32_t addr) {
    uint32_t v;
    asm volatile("ld.shared.u32 %0, [%1];" : "=r"(v) : "r"(addr));
    return v;
}

__global__ void __launch_bounds__(128, 3) gnn_warp(
    const float* __restrict__ x,
    const float* __restrict__ W1, const float* __restrict__ b1,
    const float* __restrict__ W2, const float* __restrict__ b2,
    const float* __restrict__ Wl, const float* __restrict__ bl,
    float* __restrict__ out, int nseg)
{
    __shared__ float4   w1pk[HD];     // {W1[0][c],W1[1][c],W1[2][c],b1[c]}
    __shared__ uint2    w1s[8 * 32];  // stage-1 B frags per (nb, lane)
    __shared__ uint2    hs[4 * 32];   // head B frags per (s, lane)
    __shared__ uint32_t b2h[8 * 32];  // b2 packed half2 per (nb, lane)

    const int t  = threadIdx.x;
    const int l  = t & 31;
    const int w  = t >> 5;
    const int lq = l >> 2;            // 0..7
    const int lr = l & 3;             // 0..3

    if (t < HD) {
        float4 v; v.x = W1[t]; v.y = W1[HD + t]; v.z = W1[2 * HD + t]; v.w = b1[t];
        w1pk[t] = v;
    }

    if (w == 0) {
        // ---- stage-1 B fragments (W1 hi/lo split) -> shared
        #pragma unroll
        for (int nb = 0; nb < 8; nb++) {
            int n = nb * 8 + lq;
            float w0 = W1[n], w1v = W1[HD + n], w2v = W1[2 * HD + n], bb = b1[n];
            uint32_t bhi, blo;
            if (lr == 0)      { bhi = packh2(w0, w1v);  blo = packh2(lo_of(w0), lo_of(w1v)); }
            else if (lr == 1) { bhi = packh2(w2v, bb);  blo = packh2(lo_of(w2v), lo_of(bb)); }
            else if (lr == 2) { bhi = packh2(w0, w1v);  blo = 0; }
            else              { bhi = packh2(w2v, 0.f); blo = 0; }
            w1s[nb * 32 + l] = make_uint2(bhi, blo);
        }
        // ---- head B fragments (Wl, cols 3..7 zero) -> shared
        #pragma unroll
        for (int s = 0; s < 4; s++) {
            int k0 = 16 * s + 2 * lr;
            float w00 = (lq < 3) ? Wl[k0 * 3 + lq] : 0.0f;
            float w01 = (lq < 3) ? Wl[(k0 + 1) * 3 + lq] : 0.0f;
            float w10 = (lq < 3) ? Wl[(k0 + 8) * 3 + lq] : 0.0f;
            float w11 = (lq < 3) ? Wl[(k0 + 9) * 3 + lq] : 0.0f;
            hs[s * 32 + l] = make_uint2(packh2(w00, w01), packh2(w10, w11));
        }
    } else if (w == 1) {
        // ---- b2 as half2 pairs per (nb, lane): {b2[nb*8+2lr], b2[nb*8+2lr+1]}
        #pragma unroll
        for (int nb = 0; nb < 8; nb++) {
            int c0 = nb * 8 + 2 * lr;
            b2h[nb * 32 + l] = packh2(b2[c0], b2[c0 + 1]);
        }
    }
    __syncthreads();

    const uint32_t w1s_b = smem_u32(w1s) + (uint32_t)l * 8u;
    const uint32_t hs_b  = smem_u32(hs)  + (uint32_t)l * 8u;
    const uint32_t b2h_b = smem_u32(b2h) + (uint32_t)l * 4u;

    // ---- stage-2 B fragments (W2, fp16) — register resident
    uint32_t breg[4][8][2];
    #pragma unroll
    for (int s = 0; s < 4; s++)
        #pragma unroll
        for (int nb = 0; nb < 8; nb++) {
            int n  = nb * 8 + lq;
            int k0 = 16 * s + 2 * lr;
            breg[s][nb][0] = packh2(W2[k0 * HD + n],       W2[(k0 + 1) * HD + n]);
            breg[s][nb][1] = packh2(W2[(k0 + 8) * HD + n], W2[(k0 + 9) * HD + n]);
        }

    const float bl0 = bl[0], bl1 = bl[1], bl2 = bl[2];

    // ---- contiguous run assignment (balanced remainder split)
    const int gw    = blockIdx.x * 4 + w;
    const int nwarp = gridDim.x * 4;
    const int K     = nseg / nwarp;
    const int rem   = nseg - K * nwarp;
    const int s0    = gw * K + (gw < rem ? gw : rem);
    const int s1    = s0 + K + (gw < rem ? 1 : 0);

    uint32_t zprev[8];   // carry: z of row (base-1); also row 15 between mb0->mb1

    for (int seg = s0; seg < s1; seg++) {
        const int base = seg * 32;

        // ---- per-lane ring-averaged input u (fp32), split hi/lo
        const int n  = base + l;
        const int p  = prev_node(n);
        const float ux = 0.5f * (x[3*n+0] + x[3*p+0]);
        const float uy = 0.5f * (x[3*n+1] + x[3*p+1]);
        const float uz = 0.5f * (x[3*n+2] + x[3*p+2]);
        const uint32_t uhi_xy = packh2(ux, uy);
        const uint32_t uhi_z1 = packh2(uz, 1.0f);
        const uint32_t ulo_xy = packh2(lo_of(ux), lo_of(uy));
        const uint32_t ulo_z0 = packh2(lo_of(uz), 0.0f);

        // ---- halo init only at run start or graph boundary (1 in 32 segs)
        if (seg == s0 || (base & (NPG - 1)) == 0) {
            const int H  = prev_node(base);
            const int pH = prev_node(H);
            const float hx = 0.5f * (x[3*H+0] + x[3*pH+0]);
            const float hy = 0.5f * (x[3*H+1] + x[3*pH+1]);
            const float hz = 0.5f * (x[3*H+2] + x[3*pH+2]);
            #pragma unroll
            for (int nb = 0; nb < 8; nb++) {
                int c0 = nb * 8 + 2 * lr;
                float4 wc0 = w1pk[c0];
                float4 wc1 = w1pk[c0 + 1];
                float h0 = fmaf(hx, wc0.x, fmaf(hy, wc0.y, fmaf(hz, wc0.z, wc0.w)));
                float h1 = fmaf(hx, wc1.x, fmaf(hy, wc1.y, fmaf(hz, wc1.z, wc1.w)));
                zprev[nb] = packh2(fmaxf(h0, 0.f), fmaxf(h1, 0.f));
            }
        }

        #pragma unroll
        for (int mb = 0; mb < 2; mb++) {
            const int r0 = 16 * mb + lq;
            const int r1 = r0 + 8;

            // ---- stage-1 A fragments: shuffle u from row lanes, select by lr
            uint32_t s0a = __shfl_sync(FULL, uhi_xy, r0);
            uint32_t s0b = __shfl_sync(FULL, uhi_z1, r0);
            uint32_t s0c = __shfl_sync(FULL, ulo_xy, r0);
            uint32_t s0d = __shfl_sync(FULL, ulo_z0, r0);
            uint32_t s1a = __shfl_sync(FULL, uhi_xy, r1);
            uint32_t s1b = __shfl_sync(FULL, uhi_z1, r1);
            uint32_t s1c = __shfl_sync(FULL, ulo_xy, r1);
            uint32_t s1d = __shfl_sync(FULL, ulo_z0, r1);
            uint32_t a0 = (lr == 0) ? s0a : (lr == 1) ? s0b : (lr == 2) ? s0c : s0d;
            uint32_t a1 = (lr == 0) ? s1a : (lr == 1) ? s1b : (lr == 2) ? s1c : s1d;
            uint32_t a2 = (lr == 0) ? s0a : (lr == 1) ? s0b : 0u;
            uint32_t a3 = (lr == 0) ? s1a : (lr == 1) ? s1b : 0u;

            // ---- stage-1 (per nb, transient accumulator, B from shared) -> al/ah
            uint32_t al[8], ah[8];
            #pragma unroll
            for (int nb = 0; nb < 8; nb++) {
                uint32_t wb0, wb1;
                lds_u2(w1s_b + (uint32_t)nb * 256u, wb0, wb1);
                float hD[4] = {0.f, 0.f, 0.f, 0.f};
                mma_f16(hD, a0, a1, a2, a3, wb0, wb1);
                uint32_t zl = h2relu(packh2(hD[0], hD[1]));  // row r0
                uint32_t zh = h2relu(packh2(hD[2], hD[3]));  // row r1
                uint32_t zls = __shfl_sync(FULL, zl, (l + 28) & 31);
                uint32_t zhs = __shfl_sync(FULL, zh, (l + 28) & 31);
                uint32_t zlp, zhp;
                if (lq == 0) {
                    zlp = zprev[nb];   // row -1 (carry/halo) or row 15
                    zhp = zls;         // row 16mb+7
                } else {
                    zlp = zls;
                    zhp = zhs;
                }
                zprev[nb] = zhs;       // lq==0 lanes: row 16mb+15 (-> mb1 / next seg)
                al[nb] = h2avg(zl, zlp);
                ah[nb] = h2avg(zh, zhp);
            }

            // ---- stage-2 + head, half-split; two independent head chains
            float d2a[4] = {0.f, 0.f, 0.f, 0.f};
            float d2b[4] = {0.f, 0.f, 0.f, 0.f};
            #pragma unroll
            for (int h2 = 0; h2 < 2; h2++) {
                float* d2 = h2 ? d2b : d2a;
                float dc[4][4];
                #pragma unroll
                for (int j = 0; j < 4; j++) {
                    dc[j][0] = 0.f; dc[j][1] = 0.f; dc[j][2] = 0.f; dc[j][3] = 0.f;
                }
                #pragma unroll
                for (int sp = 0; sp < 4; sp++) {
                    #pragma unroll
                    for (int j = 0; j < 4; j++) {
                        const int nb = 4 * h2 + j;
                        mma_f16(dc[j], al[2*sp], ah[2*sp], al[2*sp+1], ah[2*sp+1],
                                breg[sp][nb][0], breg[sp][nb][1]);
                    }
                }
                #pragma unroll
                for (int ss = 0; ss < 2; ss++) {
                    const int s  = 2 * h2 + ss;
                    const int j0 = 2 * ss, j1 = 2 * ss + 1;
                    const int n0 = 4 * h2 + j0, n1 = 4 * h2 + j1;
                    uint32_t bh0 = lds_u1(b2h_b + (uint32_t)n0 * 128u);
                    uint32_t bh1 = lds_u1(b2h_b + (uint32_t)n1 * 128u);
                    uint32_t e0 = h2addrelu(packh2(dc[j0][0], dc[j0][1]), bh0);
                    uint32_t e1 = h2addrelu(packh2(dc[j0][2], dc[j0][3]), bh0);
                    uint32_t e2 = h2addrelu(packh2(dc[j1][0], dc[j1][1]), bh1);
                    uint32_t e3 = h2addrelu(packh2(dc[j1][2], dc[j1][3]), bh1);
                    uint32_t hb0, hb1;
                    lds_u2(hs_b + (uint32_t)s * 256u, hb0, hb1);
                    mma_f16(d2, e0, e1, e2, e3, hb0, hb1);
                }
            }

            const int g0 = base + r0;
            const int g1 = base + r1;
            if (lr == 0) {
                out[3*g0+0] = d2a[0] + d2b[0] + bl0;
                out[3*g0+1] = d2a[1] + d2b[1] + bl1;
                out[3*g1+0] = d2a[2] + d2b[2] + bl0;
                out[3*g1+1] = d2a[3] + d2b[3] + bl1;
            } else if (lr == 1) {
                out[3*g0+2] = d2a[0] + d2b[0] + bl2;
                out[3*g1+2] = d2a[2] + d2b[2] + bl2;
            }
        }
    }
}

extern "C" void kernel_launch(void* const* d_in, const int* in_sizes, int n_in,
                              void* d_out, int out_size) {
    // metadata order: node_index, edge_index, W1, b1, W2, b2, Wl, bl
    const float* x  = (const float*)d_in[0];
    const float* W1 = (const float*)d_in[2];
    const float* b1 = (const float*)d_in[3];
    const float* W2 = (const float*)d_in[4];
    const float* b2 = (const float*)d_in[5];
    const float* Wl = (const float*)d_in[6];
    const float* bl = (const float*)d_in[7];
    float* out = (float*)d_out;

    int N    = in_sizes[0] / 3;
    int nseg = N / 32;
    int grid = 3 * 148;
    if (grid * 4 > nseg) grid = (nseg + 3) / 4;

    gnn_warp<<<grid, 128>>>(x, W1, b1, W2, b2, Wl, bl, out, nseg);
}